// round 4
// baseline (speedup 1.0000x reference)
#include <cuda_runtime.h>
#include <cuda_bf16.h>
#include <cstdint>

#define NB 16
#define NT 64
#define NF 64
#define NN 128

// ---- smem word offsets (u32 words) -----------------------------------------
// SB:  S operand, B-format [128 n][64 kp] hi/lo        (stride 68)
// M3/M2: chain intermediates, A-format [64 r][64 kp]   (stride 68)
// XA:  x row, A-format                                  (stride 68)
// ZB:  finished tap, B-format-64 [128 n][32 kp]        (stride 36)
// HA:  H chunk, A-format-64 [64 o][32 kp] (aliases M3) (stride 36)
#define SB_HI 0
#define SB_LO 8704
#define M3_HI 17408
#define M3_LO 21760
#define M2_HI 26112
#define M2_LO 30464
#define XA_HI 34816
#define XA_LO 39168
#define ZB_HI 43520
#define ZB_LO 48128
#define HA_HI M3_HI
#define HA_LO (M3_HI + 2304)
#define SMEM_WORDS 52736           // 210944 bytes

// ---------------------------------------------------------------------------
__device__ __forceinline__ uint32_t pack_hi2(float a, float b) {
    uint32_t ua = (uint32_t)__bfloat16_as_ushort(__float2bfloat16(a));
    uint32_t ub = (uint32_t)__bfloat16_as_ushort(__float2bfloat16(b));
    return (ub << 16) | ua;
}
__device__ __forceinline__ uint32_t pack_lo2(float a, float b) {
    __nv_bfloat16 ha = __float2bfloat16(a);
    __nv_bfloat16 hb = __float2bfloat16(b);
    float ra = a - __bfloat162float(ha);
    float rb = b - __bfloat162float(hb);
    uint32_t ua = (uint32_t)__bfloat16_as_ushort(__float2bfloat16(ra));
    uint32_t ub = (uint32_t)__bfloat16_as_ushort(__float2bfloat16(rb));
    return (ub << 16) | ua;
}

#define MMA_BF16(c, a0, a1, a2, a3, b0, b1)                                   \
    asm volatile(                                                             \
        "mma.sync.aligned.m16n8k16.row.col.f32.bf16.bf16.f32 "                \
        "{%0,%1,%2,%3}, {%4,%5,%6,%7}, {%8,%9}, {%0,%1,%2,%3};"               \
        : "+f"((c)[0]), "+f"((c)[1]), "+f"((c)[2]), "+f"((c)[3])              \
        : "r"(a0), "r"(a1), "r"(a2), "r"(a3), "r"(b0), "r"(b1))

// ---- fills ----------------------------------------------------------------
__device__ __forceinline__ void fill_S(uint32_t* sm, const float* __restrict__ Sp, int tid) {
    for (int i = tid; i < 128 * 64; i += 256) {
        int n = i & 127, kp = i >> 7;
        float va = Sp[(2 * kp) * NN + n];
        float vb = Sp[(2 * kp + 1) * NN + n];
        sm[SB_HI + n * 68 + kp] = pack_hi2(va, vb);
        sm[SB_LO + n * 68 + kp] = pack_lo2(va, vb);
    }
}
__device__ __forceinline__ void fill_XA(uint32_t* sm, const float* __restrict__ xp, int tid) {
    for (int i = tid; i < 64 * 64; i += 256) {
        int r = i >> 6, kp = i & 63;
        float2 v = *(const float2*)(xp + r * NN + 2 * kp);
        sm[XA_HI + r * 68 + kp] = pack_hi2(v.x, v.y);
        sm[XA_LO + r * 68 + kp] = pack_lo2(v.x, v.y);
    }
}
__device__ __forceinline__ void fill_ZB_x(uint32_t* sm, const float* __restrict__ xp, int tid) {
    for (int i = tid; i < 128 * 32; i += 256) {
        int n = i & 127, kp = i >> 7;
        float va = xp[(2 * kp) * NN + n];
        float vb = xp[(2 * kp + 1) * NN + n];
        sm[ZB_HI + n * 36 + kp] = pack_hi2(va, vb);
        sm[ZB_LO + n * 36 + kp] = pack_lo2(va, vb);
    }
}
__device__ __forceinline__ void fill_HA(uint32_t* sm, const float* __restrict__ H, int off, int tid) {
    for (int i = tid; i < 64 * 32; i += 256) {
        int o = i >> 5, kp = i & 31;
        float2 v = *(const float2*)(H + o * 512 + off + 2 * kp);
        sm[HA_HI + o * 36 + kp] = pack_hi2(v.x, v.y);
        sm[HA_LO + o * 36 + kp] = pack_lo2(v.x, v.y);
    }
}
// tap0 filter: H[:,e=0,k=0,:] + H[:,e=1,k=0,:]  (x is e-independent)
__device__ __forceinline__ void fill_HA0(uint32_t* sm, const float* __restrict__ H, int tid) {
    for (int i = tid; i < 64 * 32; i += 256) {
        int o = i >> 5, kp = i & 31;
        float2 v0 = *(const float2*)(H + o * 512 + 2 * kp);
        float2 v1 = *(const float2*)(H + o * 512 + 256 + 2 * kp);
        float a = v0.x + v1.x, b = v0.y + v1.y;
        sm[HA_HI + o * 36 + kp] = pack_hi2(a, b);
        sm[HA_LO + o * 36 + kp] = pack_lo2(a, b);
    }
}

// ---- matmuls --------------------------------------------------------------
// acc = A([64][128], A-fmt at AHI/ALO) @ S (SB, [128n][128k]); fresh acc
__device__ __forceinline__ void mma_fullK(const uint32_t* sm, int AHI, int ALO,
                                          float acc[8][4], int wm, int wn, int ra, int ca)
{
    #pragma unroll
    for (int nt = 0; nt < 8; nt++)
        acc[nt][0] = acc[nt][1] = acc[nt][2] = acc[nt][3] = 0.f;
    #pragma unroll
    for (int k = 0; k < 8; k++) {
        int ab = AHI + (16 * wm + ra) * 68 + k * 8 + ca;
        uint32_t ah0 = sm[ab],     ah1 = sm[ab + 8 * 68];
        uint32_t ah2 = sm[ab + 4], ah3 = sm[ab + 8 * 68 + 4];
        int al = ab + (ALO - AHI);
        uint32_t al0 = sm[al],     al1 = sm[al + 8 * 68];
        uint32_t al2 = sm[al + 4], al3 = sm[al + 8 * 68 + 4];
        #pragma unroll
        for (int nt = 0; nt < 8; nt++) {
            int bb = SB_HI + (64 * wn + nt * 8 + ra) * 68 + k * 8 + ca;
            uint32_t bh0 = sm[bb], bh1 = sm[bb + 4];
            uint32_t bl0 = sm[bb + (SB_LO - SB_HI)], bl1 = sm[bb + (SB_LO - SB_HI) + 4];
            MMA_BF16(acc[nt], ah0, ah1, ah2, ah3, bh0, bh1);
            MMA_BF16(acc[nt], ah0, ah1, ah2, ah3, bl0, bl1);
            MMA_BF16(acc[nt], al0, al1, al2, al3, bh0, bh1);
        }
    }
}
// accY += HA([64 o][64 f]) @ ZB([128 n][64 f])
__device__ __forceinline__ void mma_halfK(const uint32_t* sm, float accY[8][4],
                                          int wm, int wn, int ra, int ca)
{
    #pragma unroll
    for (int kk = 0; kk < 4; kk++) {
        int ab = HA_HI + (16 * wm + ra) * 36 + kk * 8 + ca;
        uint32_t ah0 = sm[ab],     ah1 = sm[ab + 8 * 36];
        uint32_t ah2 = sm[ab + 4], ah3 = sm[ab + 8 * 36 + 4];
        int al = ab + (HA_LO - HA_HI);
        uint32_t al0 = sm[al],     al1 = sm[al + 8 * 36];
        uint32_t al2 = sm[al + 4], al3 = sm[al + 8 * 36 + 4];
        #pragma unroll
        for (int nt = 0; nt < 8; nt++) {
            int bb = ZB_HI + (64 * wn + nt * 8 + ra) * 36 + kk * 8 + ca;
            uint32_t bh0 = sm[bb], bh1 = sm[bb + 4];
            uint32_t bl0 = sm[bb + (ZB_LO - ZB_HI)], bl1 = sm[bb + (ZB_LO - ZB_HI) + 4];
            MMA_BF16(accY[nt], ah0, ah1, ah2, ah3, bh0, bh1);
            MMA_BF16(accY[nt], ah0, ah1, ah2, ah3, bl0, bl1);
            MMA_BF16(accY[nt], al0, al1, al2, al3, bh0, bh1);
        }
    }
}

// ---- acc -> smem conversions ----------------------------------------------
// A-format: word (row, kp=col/2); cols per thread are even (2ca) so local pack works
__device__ __forceinline__ void conv_A(uint32_t* sm, int AHI, int ALO,
                                       const float acc[8][4], int wm, int wn, int ra, int ca)
{
    int r0 = 16 * wm + ra;
    #pragma unroll
    for (int nt = 0; nt < 8; nt++) {
        int kp = 32 * wn + 4 * nt + ca;
        sm[AHI + r0 * 68 + kp]       = pack_hi2(acc[nt][0], acc[nt][1]);
        sm[ALO + r0 * 68 + kp]       = pack_lo2(acc[nt][0], acc[nt][1]);
        sm[AHI + (r0 + 8) * 68 + kp] = pack_hi2(acc[nt][2], acc[nt][3]);
        sm[ALO + (r0 + 8) * 68 + kp] = pack_lo2(acc[nt][2], acc[nt][3]);
    }
}
// B-format-64 (transposed): word (n=col, kp=row/2). Row r0+1 lives in lane+4 -> shfl.
__device__ __forceinline__ void conv_ZB(uint32_t* sm, const float acc[8][4],
                                        int wm, int wn, int ra, int ca)
{
    #pragma unroll
    for (int nt = 0; nt < 8; nt++) {
        float o0 = __shfl_down_sync(0xffffffffu, acc[nt][0], 4);
        float o1 = __shfl_down_sync(0xffffffffu, acc[nt][1], 4);
        float o2 = __shfl_down_sync(0xffffffffu, acc[nt][2], 4);
        float o3 = __shfl_down_sync(0xffffffffu, acc[nt][3], 4);
        if (!(ra & 1)) {
            int c  = 64 * wn + nt * 8 + 2 * ca;
            int ka = 8 * wm + (ra >> 1);
            sm[ZB_HI + c * 36 + ka]           = pack_hi2(acc[nt][0], o0);
            sm[ZB_LO + c * 36 + ka]           = pack_lo2(acc[nt][0], o0);
            sm[ZB_HI + (c + 1) * 36 + ka]     = pack_hi2(acc[nt][1], o1);
            sm[ZB_LO + (c + 1) * 36 + ka]     = pack_lo2(acc[nt][1], o1);
            sm[ZB_HI + c * 36 + ka + 4]       = pack_hi2(acc[nt][2], o2);
            sm[ZB_LO + c * 36 + ka + 4]       = pack_lo2(acc[nt][2], o2);
            sm[ZB_HI + (c + 1) * 36 + ka + 4] = pack_hi2(acc[nt][3], o3);
            sm[ZB_LO + (c + 1) * 36 + ka + 4] = pack_lo2(acc[nt][3], o3);
        }
    }
}

// ---------------------------------------------------------------------------
// Fused kernel: one block per (b,t). Computes taps in-block via the chain
//   m3 = x[t-3]@S[t-2]@S[t-1]@S[t], m2 = x[t-2]@S[t-1]@S[t], m1 = x[t-1]@S[t]
// and folds each finished tap into accY += H[:,e,k,:] @ tap immediately.
// ---------------------------------------------------------------------------
__global__ void __launch_bounds__(256) fused_gf(
    const float* __restrict__ x, const float* __restrict__ S,
    const float* __restrict__ H, const float* __restrict__ bias,
    float* __restrict__ y)
{
    extern __shared__ uint32_t sm[];
    int t = blockIdx.x & 63, b = blockIdx.x >> 6;
    int tid = threadIdx.x;
    int wid = tid >> 5, lane = tid & 31;
    int wm = wid & 3, wn = wid >> 2;
    int ra = lane >> 2, ca = lane & 3;

    const float* xb = x + (size_t)b * NT * NF * NN;
    const float* Sbb = S + (size_t)b * NT * 2 * NN * NN;

    float accY[8][4];
    #pragma unroll
    for (int nt = 0; nt < 8; nt++)
        accY[nt][0] = accY[nt][1] = accY[nt][2] = accY[nt][3] = 0.f;
    float macc[8][4];

    // ---- tap0 ----
    fill_ZB_x(sm, xb + (size_t)t * NF * NN, tid);
    fill_HA0(sm, H, tid);
    __syncthreads();
    mma_halfK(sm, accY, wm, wn, ra, ca);
    __syncthreads();

    if (t > 0) {
        for (int e = 0; e < 2; e++) {
            // stage 1: M3 = x[t-3] @ S[t-2]
            if (t >= 3) {
                fill_S(sm, Sbb + (size_t)((t - 2) * 2 + e) * NN * NN, tid);
                fill_XA(sm, xb + (size_t)(t - 3) * NF * NN, tid);
                __syncthreads();
                mma_fullK(sm, XA_HI, XA_LO, macc, wm, wn, ra, ca);
                conv_A(sm, M3_HI, M3_LO, macc, wm, wn, ra, ca);
            }
            // stage 2: M3 = M3 @ S[t-1], M2 = x[t-2] @ S[t-1]
            if (t >= 2) {
                __syncthreads();
                fill_S(sm, Sbb + (size_t)((t - 1) * 2 + e) * NN * NN, tid);
                fill_XA(sm, xb + (size_t)(t - 2) * NF * NN, tid);
                __syncthreads();
                float macc2[8][4];
                if (t >= 3) mma_fullK(sm, M3_HI, M3_LO, macc, wm, wn, ra, ca);
                mma_fullK(sm, XA_HI, XA_LO, macc2, wm, wn, ra, ca);
                __syncthreads();
                if (t >= 3) conv_A(sm, M3_HI, M3_LO, macc, wm, wn, ra, ca);
                conv_A(sm, M2_HI, M2_LO, macc2, wm, wn, ra, ca);
            }
            // stage 3: multiply by S[t], fold each tap into projection
            __syncthreads();
            fill_S(sm, Sbb + (size_t)(t * 2 + e) * NN * NN, tid);
            fill_XA(sm, xb + (size_t)(t - 1) * NF * NN, tid);
            __syncthreads();
            if (t >= 3) {
                mma_fullK(sm, M3_HI, M3_LO, macc, wm, wn, ra, ca);
                __syncthreads();                       // M3 reads done (HA aliases M3)
                conv_ZB(sm, macc, wm, wn, ra, ca);
                fill_HA(sm, H, e * 256 + 3 * 64, tid);
                __syncthreads();
                mma_halfK(sm, accY, wm, wn, ra, ca);
                __syncthreads();
            }
            if (t >= 2) {
                mma_fullK(sm, M2_HI, M2_LO, macc, wm, wn, ra, ca);
                __syncthreads();
                conv_ZB(sm, macc, wm, wn, ra, ca);
                fill_HA(sm, H, e * 256 + 2 * 64, tid);
                __syncthreads();
                mma_halfK(sm, accY, wm, wn, ra, ca);
                __syncthreads();
            }
            {   // k = 1 (t >= 1 guaranteed here)
                mma_fullK(sm, XA_HI, XA_LO, macc, wm, wn, ra, ca);
                __syncthreads();
                conv_ZB(sm, macc, wm, wn, ra, ca);
                fill_HA(sm, H, e * 256 + 1 * 64, tid);
                __syncthreads();
                mma_halfK(sm, accY, wm, wn, ra, ca);
                __syncthreads();
            }
        }
    }

    // ---- store y + bias ----
    float* yp = y + (size_t)(b * NT + t) * NF * NN;
    int r0 = 16 * wm + ra;
    float bv0 = bias[r0], bv1 = bias[r0 + 8];
    #pragma unroll
    for (int nt = 0; nt < 8; nt++) {
        int c = 64 * wn + nt * 8 + 2 * ca;
        *(float2*)(yp + r0 * NN + c) =
            make_float2(accY[nt][0] + bv0, accY[nt][1] + bv0);
        *(float2*)(yp + (r0 + 8) * NN + c) =
            make_float2(accY[nt][2] + bv1, accY[nt][3] + bv1);
    }
}

// ---------------------------------------------------------------------------
extern "C" void kernel_launch(void* const* d_in, const int* in_sizes, int n_in,
                              void* d_out, int out_size)
{
    const float* x    = (const float*)d_in[0];
    const float* S    = (const float*)d_in[1];
    const float* H    = (const float*)d_in[2];
    const float* bias = (const float*)d_in[3];
    float* y = (float*)d_out;

    cudaFuncSetAttribute(fused_gf, cudaFuncAttributeMaxDynamicSharedMemorySize,
                         SMEM_WORDS * 4);
    fused_gf<<<NB * NT, 256, SMEM_WORDS * 4>>>(x, S, H, bias, y);
}